// round 2
// baseline (speedup 1.0000x reference)
#include <cuda_runtime.h>

#define NB 16
#define NL 64
#define ND 256
#define NR 8
#define NBL (NB*NL)     // 1024
#define NP (NR*ND)      // 2048

// Scratch (device globals — no runtime allocation allowed)
__device__ float g_x [NBL*ND];        // gathered embeddings      [1024,256]
__device__ float g_io[NBL*3*ND];      // in_proj: shift|scale|px  [1024,768]
__device__ float g_p [NBL*NP];        // LN'd neighbor proj       [1024,2048]
__device__ float g_h [NBL*ND];        // recurrent state y        [1024,256]
__device__ int   g_len[NB];

// ---------- packed fp32x2 helpers ----------
__device__ __forceinline__ unsigned long long pack2(float v){
    unsigned long long r;
    asm("mov.b64 %0, {%1, %1};" : "=l"(r) : "f"(v));
    return r;
}
__device__ __forceinline__ float2 unpack2(unsigned long long v){
    float2 r;
    asm("mov.b64 {%0, %1}, %2;" : "=f"(r.x), "=f"(r.y) : "l"(v));
    return r;
}
__device__ __forceinline__ void ffma2(unsigned long long& d, unsigned long long a, unsigned long long b){
    asm("fma.rn.f32x2 %0, %1, %2, %0;" : "+l"(d) : "l"(a), "l"(b));
}

// ---------- prologue ----------
__global__ void gather_init_kernel(const int* __restrict__ tokens,
                                   const float* __restrict__ emb){
    int row = blockIdx.x;            // b*64 + l
    int b = row >> 6, l = row & 63;
    int tok = tokens[l*NB + b];      // tokens layout [L,B]
    int t = threadIdx.x;
    g_x[row*ND + t] = emb[tok*ND + t];
    g_h[row*ND + t] = 0.f;
}

__global__ void length_kernel(const int* __restrict__ tokens){
    int b = threadIdx.x;
    if (b < NB){
        int c = 0;
        for (int l = 0; l < NL; l++) c += (tokens[l*NB + b] != 0);
        g_len[b] = c;
    }
}

// ---------- tiled GEMM (M=1024, K=256), BM=64, BN=256, BK=16 ----------
// out[m][n] = sum_k H[m][k]*W[k][n] + bias[n]; optional LN over each 256-col group
template<bool DO_LN>
__global__ void __launch_bounds__(256) gemm_kernel(const float* __restrict__ H,
        const float* __restrict__ W, const float* __restrict__ bias,
        float* __restrict__ out, int N)
{
    __shared__ __align__(16) unsigned long long Hs2[16][64]; // A frag pre-duplicated for f32x2
    __shared__ __align__(16) float Ws[16][256];
    const int t  = threadIdx.x;
    const int tx = t & 31, ty = t >> 5;           // warp = ty; lanes span the 256 cols
    const int m0 = blockIdx.x * 64, n0 = blockIdx.y * 256;

    unsigned long long acc[8][4];
    #pragma unroll
    for (int i = 0; i < 8; i++)
        #pragma unroll
        for (int j = 0; j < 4; j++) acc[i][j] = 0ull;

    const int lm  = t & 63;            // H loader: row within tile
    const int lk  = (t >> 6) * 4;      // H loader: 4 consecutive k
    const int ln4 = (t & 63) * 4;      // W loader: 4 consecutive n
    const int lkr = (t >> 6) * 4;      // W loader: 4 k-rows

    for (int k0 = 0; k0 < 256; k0 += 16){
        float4 hv = *(const float4*)(H + (m0+lm)*ND + k0 + lk);
        Hs2[lk+0][lm] = pack2(hv.x);
        Hs2[lk+1][lm] = pack2(hv.y);
        Hs2[lk+2][lm] = pack2(hv.z);
        Hs2[lk+3][lm] = pack2(hv.w);
        #pragma unroll
        for (int q = 0; q < 4; q++){
            float4 wv = *(const float4*)(W + (k0+lkr+q)*N + n0 + ln4);
            *(float4*)&Ws[lkr+q][ln4] = wv;
        }
        __syncthreads();
        #pragma unroll
        for (int k = 0; k < 16; k++){
            const ulonglong2* ap = (const ulonglong2*)&Hs2[k][ty*8];
            ulonglong2 a01 = ap[0], a23 = ap[1], a45 = ap[2], a67 = ap[3];
            const ulonglong2* bp2 = (const ulonglong2*)&Ws[k][tx*8];
            ulonglong2 b01 = bp2[0], b23 = bp2[1];
            unsigned long long a2[8] = {a01.x,a01.y,a23.x,a23.y,a45.x,a45.y,a67.x,a67.y};
            unsigned long long b2[4] = {b01.x,b01.y,b23.x,b23.y};
            #pragma unroll
            for (int i = 0; i < 8; i++)
                #pragma unroll
                for (int j = 0; j < 4; j++)
                    ffma2(acc[i][j], a2[i], b2[j]);
        }
        __syncthreads();
    }

    float bja[8];
    #pragma unroll
    for (int j = 0; j < 8; j++) bja[j] = bias[n0 + tx*8 + j];

    #pragma unroll
    for (int i = 0; i < 8; i++){
        float v[8];
        #pragma unroll
        for (int j = 0; j < 4; j++){
            float2 u = unpack2(acc[i][j]);
            v[2*j]   = u.x + bja[2*j];
            v[2*j+1] = u.y + bja[2*j+1];
        }
        if (DO_LN){
            // two-pass LN over the 256 cols of this row (spread across the warp)
            float s = 0.f;
            #pragma unroll
            for (int j = 0; j < 8; j++) s += v[j];
            #pragma unroll
            for (int o = 16; o > 0; o >>= 1) s += __shfl_xor_sync(0xffffffffu, s, o);
            float mean = s * (1.f/256.f);
            float q = 0.f;
            #pragma unroll
            for (int j = 0; j < 8; j++){ float d = v[j]-mean; q += d*d; }
            #pragma unroll
            for (int o = 16; o > 0; o >>= 1) q += __shfl_xor_sync(0xffffffffu, q, o);
            float r = rsqrtf(q * (1.f/256.f) + 1e-5f);
            #pragma unroll
            for (int j = 0; j < 8; j++) v[j] = (v[j]-mean)*r;
        }
        float* op = out + (m0 + ty*8 + i)*N + n0 + tx*8;
        #pragma unroll
        for (int j = 0; j < 4; j++){
            float2 o2; o2.x = v[2*j]; o2.y = v[2*j+1];
            *(float2*)(op + 2*j) = o2;
        }
    }
}

// ---------- fused step: einsum + shrink + LN/gate + out-GEMM + tanh + mask ----------
// block handles (b, 8 consecutive j); grid = 128
__global__ void __launch_bounds__(256) step_kernel(
    const float* __restrict__ A, const float* __restrict__ Wout,
    const float* __restrict__ bout, int iter)
{
    __shared__ __align__(16) union USm {
        unsigned long long As2[512][8];                         // 32 KB (phase 1)
        struct { float ls[2][8][256]; float hsm[256][10]; } p2; // 26 KB (phases 2/3)
    } sm;

    const int t  = threadIdx.x;
    const int b  = blockIdx.x >> 3;
    const int j0 = (blockIdx.x & 7) * 8;
    const int row0 = b*64 + j0;

    // stage A column block: As2[k=i*8+h][jj] = A[b, i, j0+jj, h], pre-dup for f32x2
    const float* Ab = A + b*32768 + j0*8;
    #pragma unroll
    for (int idx = 0; idx < 16; idx++){
        int e = idx*256 + t;
        int k = e >> 3, jj = e & 7;
        float a = Ab[(k >> 3)*512 + jj*8 + (k & 7)];
        sm.As2[k][jj] = pack2(a);
    }
    __syncthreads();

    // phase 1: lin_sum[jj][d] = sum_k A[k][jj] * p[b,k,d]; k split over ty halves
    const int tx = t & 127;          // d-pair
    const int ty = t >> 7;           // k half
    unsigned long long acc[8];
    #pragma unroll
    for (int jj = 0; jj < 8; jj++) acc[jj] = 0ull;
    const float* pbase = g_p + (b*512 + ty*256)*256 + tx*2;
    #pragma unroll 4
    for (int k = 0; k < 256; k++){
        unsigned long long pv = *(const unsigned long long*)(pbase + k*256);
        int ks = ty*256 + k;
        #pragma unroll
        for (int jj = 0; jj < 8; jj++) ffma2(acc[jj], sm.As2[ks][jj], pv);
    }
    __syncthreads();   // all As2 reads complete before union is reused
    #pragma unroll
    for (int jj = 0; jj < 8; jj++){
        float2 u = unpack2(acc[jj]);
        sm.p2.ls[ty][jj][2*tx]   = u.x;
        sm.p2.ls[ty][jj][2*tx+1] = u.y;
    }
    __syncthreads();

    // phase 2: shrink + proj_x + LN + gate; warp r owns row j0+r
    const int r = t >> 5, lane = t & 31;
    const int row = row0 + r;
    const float* iorow = g_io + row*768;   // [0:256)=shift [256:512)=scale [512:768)=proj_x
    float hv[8];
    float s = 0.f;
    #pragma unroll
    for (int qq = 0; qq < 8; qq++){
        int d = qq*32 + lane;
        float x = sm.p2.ls[0][r][d] + sm.p2.ls[1][r][d];
        x = x - tanhf(x);              // shrink (accurate tanh: cancellation near 0)
        x += iorow[512 + d];           // + proj_x
        hv[qq] = x;
        s += x;
    }
    #pragma unroll
    for (int o = 16; o > 0; o >>= 1) s += __shfl_xor_sync(0xffffffffu, s, o);
    float mean = s * (1.f/256.f);
    float q = 0.f;
    #pragma unroll
    for (int qq = 0; qq < 8; qq++){ float d = hv[qq]-mean; q += d*d; }
    #pragma unroll
    for (int o = 16; o > 0; o >>= 1) q += __shfl_xor_sync(0xffffffffu, q, o);
    float rr = rsqrtf(q * (1.f/256.f) + 1e-5f);
    #pragma unroll
    for (int qq = 0; qq < 8; qq++){
        int d = qq*32 + lane;
        float lnv = (hv[qq]-mean)*rr;
        float g = fmaf(iorow[d], lnv, iorow[256+d]);   // shift*ln + scale
        sm.p2.hsm[d][r] = fmaxf(g, 0.f);               // relu -> h
    }
    __syncthreads();

    // phase 3: y[r][n] = tanh( sum_k h[r][k]*Wout[k][n] + bout[n] ), rows paired for f32x2
    unsigned long long yacc[4] = {0ull, 0ull, 0ull, 0ull};
    #pragma unroll 4
    for (int k = 0; k < 256; k++){
        unsigned long long w2 = pack2(Wout[k*256 + t]);
        const unsigned long long* hp = (const unsigned long long*)&sm.p2.hsm[k][0];
        ffma2(yacc[0], hp[0], w2);
        ffma2(yacc[1], hp[1], w2);
        ffma2(yacc[2], hp[2], w2);
        ffma2(yacc[3], hp[3], w2);
    }
    float bo = bout[t];
    bool masked = (iter > g_len[b]);
    #pragma unroll
    for (int qq = 0; qq < 4; qq++){
        float2 u = unpack2(yacc[qq]);
        float y0 = masked ? 0.f : tanhf(u.x + bo);
        float y1 = masked ? 0.f : tanhf(u.y + bo);
        g_h[(row0 + 2*qq    )*256 + t] = y0;
        g_h[(row0 + 2*qq + 1)*256 + t] = y1;
    }
}

// ---------- epilogue: final[b][d] = sum_i h[b,i,d]*root[b,i] ----------
__global__ void finalize_kernel(const float* __restrict__ root, float* __restrict__ out){
    int b = blockIdx.x, t = threadIdx.x;
    float s = 0.f;
    #pragma unroll 8
    for (int i = 0; i < 64; i++)
        s += g_h[(b*64 + i)*256 + t] * root[b*64 + i];
    out[b*256 + t] = s;
}

extern "C" void kernel_launch(void* const* d_in, const int* in_sizes, int n_in,
                              void* d_out, int out_size)
{
    const int*   tokens = (const int*)  d_in[0];
    const float* A      = (const float*)d_in[1];
    const float* root   = (const float*)d_in[2];
    const float* emb    = (const float*)d_in[3];
    const float* Wp     = (const float*)d_in[4];
    const float* bp     = (const float*)d_in[5];
    const float* Win    = (const float*)d_in[6];
    const float* bin    = (const float*)d_in[7];
    const float* Wout   = (const float*)d_in[8];
    const float* bout   = (const float*)d_in[9];
    float* out = (float*)d_out;

    float *px, *pio, *pp, *ph;
    cudaGetSymbolAddress((void**)&px,  g_x);
    cudaGetSymbolAddress((void**)&pio, g_io);
    cudaGetSymbolAddress((void**)&pp,  g_p);
    cudaGetSymbolAddress((void**)&ph,  g_h);

    gather_init_kernel<<<NBL, ND>>>(tokens, emb);
    length_kernel<<<1, NB>>>(tokens);
    gemm_kernel<false><<<dim3(16, 3), 256>>>(px, Win, bin, pio, 768);   // hoisted in_proj

    for (int it = 0; it < 64; it++){
        int i = 64 - it;                                                // i = L..1
        gemm_kernel<true><<<dim3(16, 8), 256>>>(ph, Wp, bp, pp, 2048);  // p = LN(h@Wp + bp)
        step_kernel<<<128, 256>>>(A, Wout, bout, i);                    // einsum..mask -> h
    }

    finalize_kernel<<<16, 256>>>(root, out);
}

// round 3
// speedup vs baseline: 1.5162x; 1.5162x over previous
#include <cuda_runtime.h>

#define NB 16
#define NL 64
#define ND 256
#define NR 8
#define NBL (NB*NL)     // 1024
#define NP (NR*ND)      // 2048

__device__ float g_x [NBL*ND];
__device__ float g_io[NBL*3*ND];      // shift|scale|proj_x
__device__ float g_p [NBL*NP];
__device__ float g_h [NBL*ND];
__device__ int   g_len[NB];

__device__ __forceinline__ unsigned long long pack2(float v){
    unsigned long long r;
    asm("mov.b64 %0, {%1, %1};" : "=l"(r) : "f"(v));
    return r;
}
__device__ __forceinline__ float2 unpack2(unsigned long long v){
    float2 r;
    asm("mov.b64 {%0, %1}, %2;" : "=f"(r.x), "=f"(r.y) : "l"(v));
    return r;
}
__device__ __forceinline__ void ffma2(unsigned long long& d, unsigned long long a, unsigned long long b){
    asm("fma.rn.f32x2 %0, %1, %2, %0;" : "+l"(d) : "l"(a), "l"(b));
}

// ---------- prologue ----------
__global__ void gather_init_kernel(const int* __restrict__ tokens,
                                   const float* __restrict__ emb){
    int row = blockIdx.x;
    int b = row >> 6, l = row & 63;
    int tok = tokens[l*NB + b];
    int t = threadIdx.x;
    g_x[row*ND + t] = emb[tok*ND + t];
    g_h[row*ND + t] = 0.f;
}

__global__ void length_kernel(const int* __restrict__ tokens){
    int b = threadIdx.x;
    if (b < NB){
        int c = 0;
        for (int l = 0; l < NL; l++) c += (tokens[l*NB + b] != 0);
        g_len[b] = c;
    }
}

// ---------- GEMM v2: M=1024,K=256; BM=64,BN=256,BK=32, 512 thr, 8x4/thread ----------
template<bool DO_LN>
__global__ void __launch_bounds__(512) gemm_kernel(const float* __restrict__ H,
        const float* __restrict__ W, const float* __restrict__ bias,
        float* __restrict__ out, int N)
{
    __shared__ __align__(16) float Hs[32*64];    // [k][m swizzled]
    __shared__ __align__(16) float Ws[32*256];   // [k][n]
    __shared__ float red[16][16];

    const int t  = threadIdx.x;
    const int tn = t & 63;           // cols tn*4..+3
    const int tm = t >> 6;           // rows tm*8..+7
    const int m0 = blockIdx.x * 64;
    const int n0 = blockIdx.y * 256;

    const int hr = t >> 3;           // H loader row 0..63
    const int hc = (t & 7) * 4;      // H loader k base
    const int wk = t >> 4;           // W loader k 0..31
    const int wc = t & 15;           // W loader col grp

    const float* Hg = H + (m0 + hr)*ND + hc;
    const float* Wg = W + (size_t)wk*N + n0 + wc*4;

    unsigned long long acc[8][2];
    #pragma unroll
    for (int i = 0; i < 8; i++){ acc[i][0] = 0ull; acc[i][1] = 0ull; }

    float4 hreg  = *(const float4*)Hg;
    float4 wreg0 = *(const float4*)(Wg);
    float4 wreg1 = *(const float4*)(Wg + 64);
    float4 wreg2 = *(const float4*)(Wg + 128);
    float4 wreg3 = *(const float4*)(Wg + 192);

    for (int s = 0; s < 8; s++){
        {   // stage to smem; A store k-swizzled (conflict-free)
            const float* hv = (const float*)&hreg;
            #pragma unroll
            for (int i = 0; i < 4; i++){
                int k = hc + i;
                Hs[k*64 + (((hr>>2) ^ ((k>>2)&15))<<2) + (hr&3)] = hv[i];
            }
            *(float4*)&Ws[wk*256 + wc*4      ] = wreg0;
            *(float4*)&Ws[wk*256 + wc*4 +  64] = wreg1;
            *(float4*)&Ws[wk*256 + wc*4 + 128] = wreg2;
            *(float4*)&Ws[wk*256 + wc*4 + 192] = wreg3;
        }
        __syncthreads();
        if (s < 7){
            const float* Hg2 = Hg + (s+1)*32;
            const float* Wg2 = Wg + (size_t)(s+1)*32*N;
            hreg  = *(const float4*)Hg2;
            wreg0 = *(const float4*)(Wg2);
            wreg1 = *(const float4*)(Wg2 + 64);
            wreg2 = *(const float4*)(Wg2 + 128);
            wreg3 = *(const float4*)(Wg2 + 192);
        }
        #pragma unroll 8
        for (int k = 0; k < 32; k++){
            const int sw = (k>>2) & 15;
            float4 a0 = *(const float4*)&Hs[k*64 + (((tm*2  ) ^ sw)<<2)];
            float4 a1 = *(const float4*)&Hs[k*64 + (((tm*2+1) ^ sw)<<2)];
            ulonglong2 bb = *(const ulonglong2*)&Ws[k*256 + tn*4];
            unsigned long long aa;
            aa = pack2(a0.x); ffma2(acc[0][0],aa,bb.x); ffma2(acc[0][1],aa,bb.y);
            aa = pack2(a0.y); ffma2(acc[1][0],aa,bb.x); ffma2(acc[1][1],aa,bb.y);
            aa = pack2(a0.z); ffma2(acc[2][0],aa,bb.x); ffma2(acc[2][1],aa,bb.y);
            aa = pack2(a0.w); ffma2(acc[3][0],aa,bb.x); ffma2(acc[3][1],aa,bb.y);
            aa = pack2(a1.x); ffma2(acc[4][0],aa,bb.x); ffma2(acc[4][1],aa,bb.y);
            aa = pack2(a1.y); ffma2(acc[5][0],aa,bb.x); ffma2(acc[5][1],aa,bb.y);
            aa = pack2(a1.z); ffma2(acc[6][0],aa,bb.x); ffma2(acc[6][1],aa,bb.y);
            aa = pack2(a1.w); ffma2(acc[7][0],aa,bb.x); ffma2(acc[7][1],aa,bb.y);
        }
        __syncthreads();
    }

    float bv[4];
    #pragma unroll
    for (int j = 0; j < 4; j++) bv[j] = bias[n0 + tn*4 + j];

    float v[8][4];
    #pragma unroll
    for (int i = 0; i < 8; i++){
        float2 u0 = unpack2(acc[i][0]);
        float2 u1 = unpack2(acc[i][1]);
        v[i][0] = u0.x + bv[0]; v[i][1] = u0.y + bv[1];
        v[i][2] = u1.x + bv[2]; v[i][3] = u1.y + bv[3];
    }

    if (DO_LN){
        float s1[8], s2[8];
        #pragma unroll
        for (int i = 0; i < 8; i++){
            s1[i] = v[i][0] + v[i][1] + v[i][2] + v[i][3];
            s2[i] = v[i][0]*v[i][0] + v[i][1]*v[i][1] + v[i][2]*v[i][2] + v[i][3]*v[i][3];
        }
        #pragma unroll
        for (int o = 16; o > 0; o >>= 1){
            #pragma unroll
            for (int i = 0; i < 8; i++){
                s1[i] += __shfl_xor_sync(0xffffffffu, s1[i], o);
                s2[i] += __shfl_xor_sync(0xffffffffu, s2[i], o);
            }
        }
        const int w = t >> 5;
        if ((t & 31) == 0){
            #pragma unroll
            for (int i = 0; i < 8; i++){ red[w][i] = s1[i]; red[w][8+i] = s2[i]; }
        }
        __syncthreads();
        const int sib = w ^ 1;   // warps 2u,2u+1 share rows tm=u
        #pragma unroll
        for (int i = 0; i < 8; i++){
            float tot1 = s1[i] + red[sib][i];
            float tot2 = s2[i] + red[sib][8+i];
            float mean = tot1 * (1.f/256.f);
            float var  = tot2 * (1.f/256.f) - mean*mean;
            float rstd = rsqrtf(var + 1e-5f);
            #pragma unroll
            for (int j = 0; j < 4; j++) v[i][j] = (v[i][j] - mean) * rstd;
        }
    }

    #pragma unroll
    for (int i = 0; i < 8; i++){
        float4 o4; o4.x = v[i][0]; o4.y = v[i][1]; o4.z = v[i][2]; o4.w = v[i][3];
        *(float4*)(out + (size_t)(m0 + tm*8 + i)*N + n0 + tn*4) = o4;
    }
}

// ---------- fused step v2: block=(b, 8 j), 512 threads, grid=128 ----------
__global__ void __launch_bounds__(512) step_kernel(
    const float* __restrict__ A, const float* __restrict__ Wout,
    const float* __restrict__ bout, int iter)
{
    __shared__ __align__(16) union USm {
        unsigned long long As2[512][8];                          // 32 KB
        struct { float ls[4][8][256]; float hsm[256][12]; } p2;  // 44 KB
    } sm;

    const int t  = threadIdx.x;
    const int b  = blockIdx.x >> 3;
    const int j0 = (blockIdx.x & 7) * 8;
    const int row0 = b*64 + j0;

    // stage A: As2[k=i*8+h][jj] = A[b, i, j0+jj, h], pre-dup for f32x2
    const float* Ab = A + b*32768 + j0*8;
    #pragma unroll
    for (int idx = 0; idx < 8; idx++){
        int e = idx*512 + t;
        int k = e >> 3, jj = e & 7;
        sm.As2[k][jj] = pack2(Ab[(k >> 3)*512 + jj*8 + (k & 7)]);
    }
    __syncthreads();

    // phase 1: lin_sum[jj][d] = sum_k A[k][jj]*p[b,k,d]; 4-way k split
    const int tx = t & 127;          // d-pair
    const int ty = t >> 7;           // k quarter
    unsigned long long acc[8];
    #pragma unroll
    for (int jj = 0; jj < 8; jj++) acc[jj] = 0ull;
    const float* pbase = g_p + (size_t)(b*512 + ty*128)*256 + tx*2;
    #pragma unroll 4
    for (int k = 0; k < 128; k++){
        unsigned long long pv = *(const unsigned long long*)(pbase + k*256);
        const int ks = ty*128 + k;
        #pragma unroll
        for (int jj = 0; jj < 8; jj++) ffma2(acc[jj], sm.As2[ks][jj], pv);
    }
    __syncthreads();   // As2 reads done before union reuse
    #pragma unroll
    for (int jj = 0; jj < 8; jj++){
        float2 u = unpack2(acc[jj]);
        *(float2*)&sm.p2.ls[ty][jj][2*tx] = u;
    }
    __syncthreads();

    // phase 2: shrink + proj_x + LN + gate + relu; warps 0..7, one row each
    const int w = t >> 5, lane = t & 31;
    if (w < 8){
        const int r = w;
        const float* iorow = g_io + (size_t)(row0 + r)*768;
        float hv[8];
        float s = 0.f;
        #pragma unroll
        for (int qq = 0; qq < 8; qq++){
            int d = qq*32 + lane;
            float x = sm.p2.ls[0][r][d] + sm.p2.ls[1][r][d]
                    + sm.p2.ls[2][r][d] + sm.p2.ls[3][r][d];
            x = x - tanhf(x);
            x += iorow[512 + d];
            hv[qq] = x;
            s += x;
        }
        #pragma unroll
        for (int o = 16; o > 0; o >>= 1) s += __shfl_xor_sync(0xffffffffu, s, o);
        float mean = s * (1.f/256.f);
        float q = 0.f;
        #pragma unroll
        for (int qq = 0; qq < 8; qq++){ float d = hv[qq]-mean; q += d*d; }
        #pragma unroll
        for (int o = 16; o > 0; o >>= 1) q += __shfl_xor_sync(0xffffffffu, q, o);
        float rr = rsqrtf(q * (1.f/256.f) + 1e-5f);
        #pragma unroll
        for (int qq = 0; qq < 8; qq++){
            int d = qq*32 + lane;
            float lnv = (hv[qq]-mean)*rr;
            float g = fmaf(iorow[d], lnv, iorow[256+d]);
            sm.p2.hsm[d][r] = fmaxf(g, 0.f);
        }
    }
    __syncthreads();

    // phase 3: y = tanh(h @ Wout + b); rows f32x2-paired, 2 row-pairs/thread
    const int n  = t & 255;
    const int g2 = t >> 8;                       // 0: rows 0-3, 1: rows 4-7
    unsigned long long yacc[2] = {0ull, 0ull};
    #pragma unroll 4
    for (int k = 0; k < 256; k++){
        unsigned long long w2 = pack2(Wout[k*256 + n]);
        const unsigned long long* hp = (const unsigned long long*)&sm.p2.hsm[k][0];
        ffma2(yacc[0], hp[g2*2 + 0], w2);
        ffma2(yacc[1], hp[g2*2 + 1], w2);
    }
    float bo = bout[n];
    bool masked = (iter > g_len[b]);
    #pragma unroll
    for (int qq = 0; qq < 2; qq++){
        float2 u = unpack2(yacc[qq]);
        float y0 = masked ? 0.f : tanhf(u.x + bo);
        float y1 = masked ? 0.f : tanhf(u.y + bo);
        g_h[(size_t)(row0 + 4*g2 + 2*qq    )*256 + n] = y0;
        g_h[(size_t)(row0 + 4*g2 + 2*qq + 1)*256 + n] = y1;
    }
}

// ---------- epilogue ----------
__global__ void finalize_kernel(const float* __restrict__ root, float* __restrict__ out){
    int b = blockIdx.x, t = threadIdx.x;
    float s = 0.f;
    #pragma unroll 8
    for (int i = 0; i < 64; i++)
        s += g_h[(b*64 + i)*256 + t] * root[b*64 + i];
    out[b*256 + t] = s;
}

extern "C" void kernel_launch(void* const* d_in, const int* in_sizes, int n_in,
                              void* d_out, int out_size)
{
    const int*   tokens = (const int*)  d_in[0];
    const float* A      = (const float*)d_in[1];
    const float* root   = (const float*)d_in[2];
    const float* emb    = (const float*)d_in[3];
    const float* Wp     = (const float*)d_in[4];
    const float* bp     = (const float*)d_in[5];
    const float* Win    = (const float*)d_in[6];
    const float* bin    = (const float*)d_in[7];
    const float* Wout   = (const float*)d_in[8];
    const float* bout   = (const float*)d_in[9];
    float* out = (float*)d_out;

    float *px, *pio, *pp, *ph;
    cudaGetSymbolAddress((void**)&px,  g_x);
    cudaGetSymbolAddress((void**)&pio, g_io);
    cudaGetSymbolAddress((void**)&pp,  g_p);
    cudaGetSymbolAddress((void**)&ph,  g_h);

    gather_init_kernel<<<NBL, ND>>>(tokens, emb);
    length_kernel<<<1, NB>>>(tokens);
    gemm_kernel<false><<<dim3(16, 3), 512>>>(px, Win, bin, pio, 768);

    for (int it = 0; it < 64; it++){
        int i = 64 - it;
        gemm_kernel<true><<<dim3(16, 8), 512>>>(ph, Wp, bp, pp, 2048);
        step_kernel<<<128, 512>>>(A, Wout, bout, i);
    }

    finalize_kernel<<<16, 256>>>(root, out);
}

// round 4
// speedup vs baseline: 1.5169x; 1.0004x over previous
#include <cuda_runtime.h>

#define NB 16
#define NL 64
#define ND 256
#define NR 8
#define NBL (NB*NL)     // 1024
#define NP (NR*ND)      // 2048

__device__ float g_x [NBL*ND];
__device__ float g_io[NBL*3*ND];      // shift|scale|proj_x
__device__ float g_p [NBL*NP];
__device__ float g_h [NBL*ND];
__device__ int   g_len[NB];

__device__ __forceinline__ unsigned long long pack2(float v){
    unsigned long long r;
    asm("mov.b64 %0, {%1, %1};" : "=l"(r) : "f"(v));
    return r;
}
__device__ __forceinline__ unsigned long long packxy(float x, float y){
    unsigned long long r;
    asm("mov.b64 %0, {%1, %2};" : "=l"(r) : "f"(x), "f"(y));
    return r;
}
__device__ __forceinline__ float2 unpack2(unsigned long long v){
    float2 r;
    asm("mov.b64 {%0, %1}, %2;" : "=f"(r.x), "=f"(r.y) : "l"(v));
    return r;
}
__device__ __forceinline__ void ffma2(unsigned long long& d, unsigned long long a, unsigned long long b){
    asm("fma.rn.f32x2 %0, %1, %2, %0;" : "+l"(d) : "l"(a), "l"(b));
}
__device__ __forceinline__ void cpa16(void* s, const void* g){
    unsigned ss = (unsigned)__cvta_generic_to_shared(s);
    asm volatile("cp.async.cg.shared.global [%0], [%1], 16;\n" :: "r"(ss), "l"(g));
}
#define CPA_COMMIT() asm volatile("cp.async.commit_group;\n" ::: "memory")
#define CPA_WAIT0()  asm volatile("cp.async.wait_group 0;\n" ::: "memory")

// ---------- prologue ----------
__global__ void gather_init_kernel(const int* __restrict__ tokens,
                                   const float* __restrict__ emb){
    int row = blockIdx.x;
    int b = row >> 6, l = row & 63;
    int tok = tokens[l*NB + b];
    int t = threadIdx.x;
    g_x[row*ND + t] = emb[tok*ND + t];
    g_h[row*ND + t] = 0.f;
}

__global__ void length_kernel(const int* __restrict__ tokens){
    int b = threadIdx.x;
    if (b < NB){
        int c = 0;
        for (int l = 0; l < NL; l++) c += (tokens[l*NB + b] != 0);
        g_len[b] = c;
    }
}

// ---------- GEMM v3: M=1024,K=256; BM=64,BN=256,BK=16, 256 thr, 8x8/thread ----------
// cp.async double-buffered W, reg-staged transposed H, conflict-free LDS.
template<bool DO_LN>
__global__ void __launch_bounds__(256) gemm_kernel(const float* __restrict__ H,
        const float* __restrict__ W, const float* __restrict__ bias,
        float* __restrict__ out, int N)
{
    __shared__ __align__(16) float Hs[2][16*64];     // [k][m-group swizzled]
    __shared__ __align__(16) float Ws[2][16*256];    // [k][n]

    const int t  = threadIdx.x;
    const int tn = t & 31;            // col groups: tn*4 and 128+tn*4
    const int tm = t >> 5;            // rows tm*8..+7 (warp id)
    const int m0 = blockIdx.x * 64;
    const int n0 = blockIdx.y * 256;

    const int hr  = t & 63;           // H loader row
    const int hc4 = (t >> 6) * 4;     // H loader k base
    const int wk  = t >> 4;           // W loader k row 0..15
    const int wn  = (t & 15) * 16;    // W loader col base

    const float* Hg = H + (size_t)(m0 + hr)*256 + hc4;
    const float* Wg = W + (size_t)wk*N + n0 + wn;

    unsigned long long acc[8][4];
    #pragma unroll
    for (int i = 0; i < 8; i++)
        #pragma unroll
        for (int j = 0; j < 4; j++) acc[i][j] = 0ull;

    // prologue: stage 0
    float4 hv = *(const float4*)Hg;
    #pragma unroll
    for (int j = 0; j < 4; j++) cpa16(&Ws[0][wk*256 + wn + j*4], Wg + j*4);
    CPA_COMMIT();
    {
        const float* hp = (const float*)&hv;
        #pragma unroll
        for (int i = 0; i < 4; i++){
            int k = hc4 + i;
            Hs[0][k*64 + ((((hr>>2) ^ k) & 15)<<2) + (hr&3)] = hp[i];
        }
    }
    hv = *(const float4*)(Hg + 16);
    CPA_WAIT0();
    __syncthreads();

    for (int s = 0; s < 16; s++){
        const int cur = s & 1;
        if (s + 1 < 16){
            const int nxt = cur ^ 1;
            const float* Wg2 = Wg + (size_t)(s+1)*16*N;
            #pragma unroll
            for (int j = 0; j < 4; j++) cpa16(&Ws[nxt][wk*256 + wn + j*4], Wg2 + j*4);
            CPA_COMMIT();
            const float* hp = (const float*)&hv;
            #pragma unroll
            for (int i = 0; i < 4; i++){
                int k = hc4 + i;
                Hs[nxt][k*64 + ((((hr>>2) ^ k) & 15)<<2) + (hr&3)] = hp[i];
            }
            if (s + 2 < 16) hv = *(const float4*)(Hg + (s+2)*16);
        }
        #pragma unroll
        for (int k = 0; k < 16; k++){
            float4 a0 = *(const float4*)&Hs[cur][k*64 + (((2*tm  ) ^ k)<<2)];
            float4 a1 = *(const float4*)&Hs[cur][k*64 + (((2*tm+1) ^ k)<<2)];
            ulonglong2 b01 = *(const ulonglong2*)&Ws[cur][k*256 + tn*4];        // cols tn*4..+3
            ulonglong2 b23 = *(const ulonglong2*)&Ws[cur][k*256 + 128 + tn*4];  // cols 128+tn*4..+3
            unsigned long long aa;
            aa = pack2(a0.x); ffma2(acc[0][0],aa,b01.x); ffma2(acc[0][1],aa,b01.y); ffma2(acc[0][2],aa,b23.x); ffma2(acc[0][3],aa,b23.y);
            aa = pack2(a0.y); ffma2(acc[1][0],aa,b01.x); ffma2(acc[1][1],aa,b01.y); ffma2(acc[1][2],aa,b23.x); ffma2(acc[1][3],aa,b23.y);
            aa = pack2(a0.z); ffma2(acc[2][0],aa,b01.x); ffma2(acc[2][1],aa,b01.y); ffma2(acc[2][2],aa,b23.x); ffma2(acc[2][3],aa,b23.y);
            aa = pack2(a0.w); ffma2(acc[3][0],aa,b01.x); ffma2(acc[3][1],aa,b01.y); ffma2(acc[3][2],aa,b23.x); ffma2(acc[3][3],aa,b23.y);
            aa = pack2(a1.x); ffma2(acc[4][0],aa,b01.x); ffma2(acc[4][1],aa,b01.y); ffma2(acc[4][2],aa,b23.x); ffma2(acc[4][3],aa,b23.y);
            aa = pack2(a1.y); ffma2(acc[5][0],aa,b01.x); ffma2(acc[5][1],aa,b01.y); ffma2(acc[5][2],aa,b23.x); ffma2(acc[5][3],aa,b23.y);
            aa = pack2(a1.z); ffma2(acc[6][0],aa,b01.x); ffma2(acc[6][1],aa,b01.y); ffma2(acc[6][2],aa,b23.x); ffma2(acc[6][3],aa,b23.y);
            aa = pack2(a1.w); ffma2(acc[7][0],aa,b01.x); ffma2(acc[7][1],aa,b01.y); ffma2(acc[7][2],aa,b23.x); ffma2(acc[7][3],aa,b23.y);
        }
        CPA_WAIT0();
        __syncthreads();
    }

    float bv[8];
    #pragma unroll
    for (int j = 0; j < 4; j++){
        bv[j]   = bias[n0 + tn*4 + j];
        bv[4+j] = bias[n0 + 128 + tn*4 + j];
    }

    float v[8][8];
    #pragma unroll
    for (int i = 0; i < 8; i++){
        #pragma unroll
        for (int j = 0; j < 4; j++){
            float2 u = unpack2(acc[i][j]);
            v[i][2*j]   = u.x + bv[2*j];
            v[i][2*j+1] = u.y + bv[2*j+1];
        }
    }

    if (DO_LN){
        // each warp owns rows tm*8..+7 entirely (lanes span all 256 cols)
        float s1[8], s2[8];
        #pragma unroll
        for (int i = 0; i < 8; i++){
            float a = 0.f, q = 0.f;
            #pragma unroll
            for (int j = 0; j < 8; j++){ a += v[i][j]; q += v[i][j]*v[i][j]; }
            s1[i] = a; s2[i] = q;
        }
        #pragma unroll
        for (int o = 16; o > 0; o >>= 1){
            #pragma unroll
            for (int i = 0; i < 8; i++){
                s1[i] += __shfl_xor_sync(0xffffffffu, s1[i], o);
                s2[i] += __shfl_xor_sync(0xffffffffu, s2[i], o);
            }
        }
        #pragma unroll
        for (int i = 0; i < 8; i++){
            float mean = s1[i] * (1.f/256.f);
            float var  = s2[i] * (1.f/256.f) - mean*mean;
            float rstd = rsqrtf(var + 1e-5f);
            #pragma unroll
            for (int j = 0; j < 8; j++) v[i][j] = (v[i][j] - mean) * rstd;
        }
    }

    #pragma unroll
    for (int i = 0; i < 8; i++){
        float* op = out + (size_t)(m0 + tm*8 + i)*N + n0;
        float4 o0; o0.x=v[i][0]; o0.y=v[i][1]; o0.z=v[i][2]; o0.w=v[i][3];
        float4 o1; o1.x=v[i][4]; o1.y=v[i][5]; o1.z=v[i][6]; o1.w=v[i][7];
        *(float4*)(op + tn*4)       = o0;
        *(float4*)(op + 128 + tn*4) = o1;
    }
}

// ---------- fused step v3: block=(b, 8 j), 512 threads, grid=128 ----------
__global__ void __launch_bounds__(512) step_kernel(
    const float* __restrict__ A, const float* __restrict__ Wout,
    const float* __restrict__ bout, int iter)
{
    __shared__ __align__(16) union USm {
        unsigned long long As[256][8];                           // k-pair packed, 16 KB
        struct { float ls[4][8][256]; float hsm[256][12]; } p2;  // 32 + 12 KB
    } sm;

    const int t  = threadIdx.x;
    const int b  = blockIdx.x >> 3;
    const int j0 = (blockIdx.x & 7) * 8;
    const int row0 = b*64 + j0;

    // stage A packed over k-pairs: As[kp][jj] = (A[b,k0,j,h], A[b,k1,j,h]) with k=i*8+h
    const float* Ab = A + b*32768 + j0*8;
    #pragma unroll
    for (int idx = 0; idx < 4; idx++){
        int e = idx*512 + t;
        int kp = e >> 3, jj = e & 7;
        int k0 = kp*2;                 // k0 even -> k0,k0+1 share the same i
        int base = (k0 >> 3)*512 + jj*8 + (k0 & 7);
        sm.As[kp][jj] = packxy(Ab[base], Ab[base + 1]);
    }
    __syncthreads();

    // phase 1: lin_sum[jj][d] += A(k-pair) * p(k-pair), FFMA2 packed over k
    const int tx = t & 127;          // d0 = tx, d1 = tx+128
    const int ty = t >> 7;           // k-quarter
    unsigned long long acc[8][2];
    #pragma unroll
    for (int jj = 0; jj < 8; jj++){ acc[jj][0] = 0ull; acc[jj][1] = 0ull; }

    const float* pb = g_p + (size_t)(b*64 + ty*16)*2048 + tx;
    #pragma unroll 2
    for (int ii = 0; ii < 16; ii++){
        const float* pr = pb + ii*2048;
        #pragma unroll
        for (int hp = 0; hp < 4; hp++){
            float pe0 = pr[hp*512];
            float po0 = pr[hp*512 + 256];
            float pe1 = pr[hp*512 + 128];
            float po1 = pr[hp*512 + 384];
            unsigned long long p0 = packxy(pe0, po0);
            unsigned long long p1 = packxy(pe1, po1);
            const int kp = (ty*16 + ii)*4 + hp;
            ulonglong2 A01 = *(const ulonglong2*)&sm.As[kp][0];
            ulonglong2 A23 = *(const ulonglong2*)&sm.As[kp][2];
            ulonglong2 A45 = *(const ulonglong2*)&sm.As[kp][4];
            ulonglong2 A67 = *(const ulonglong2*)&sm.As[kp][6];
            ffma2(acc[0][0], A01.x, p0); ffma2(acc[0][1], A01.x, p1);
            ffma2(acc[1][0], A01.y, p0); ffma2(acc[1][1], A01.y, p1);
            ffma2(acc[2][0], A23.x, p0); ffma2(acc[2][1], A23.x, p1);
            ffma2(acc[3][0], A23.y, p0); ffma2(acc[3][1], A23.y, p1);
            ffma2(acc[4][0], A45.x, p0); ffma2(acc[4][1], A45.x, p1);
            ffma2(acc[5][0], A45.y, p0); ffma2(acc[5][1], A45.y, p1);
            ffma2(acc[6][0], A67.x, p0); ffma2(acc[6][1], A67.x, p1);
            ffma2(acc[7][0], A67.y, p0); ffma2(acc[7][1], A67.y, p1);
        }
    }
    __syncthreads();   // all As reads complete before union reuse
    #pragma unroll
    for (int jj = 0; jj < 8; jj++){
        float2 u0 = unpack2(acc[jj][0]);
        float2 u1 = unpack2(acc[jj][1]);
        sm.p2.ls[ty][jj][tx]       = u0.x + u0.y;
        sm.p2.ls[ty][jj][tx + 128] = u1.x + u1.y;
    }
    __syncthreads();

    // phase 2: shrink + proj_x + LN + gate + relu; warps 0..7 own one row each
    const int w = t >> 5, lane = t & 31;
    if (w < 8){
        const int r = w;
        const float* iorow = g_io + (size_t)(row0 + r)*768;
        float hv2[8];
        float s = 0.f;
        #pragma unroll
        for (int qq = 0; qq < 8; qq++){
            int d = qq*32 + lane;
            float x = sm.p2.ls[0][r][d] + sm.p2.ls[1][r][d]
                    + sm.p2.ls[2][r][d] + sm.p2.ls[3][r][d];
            x = x - tanhf(x);
            x += iorow[512 + d];
            hv2[qq] = x;
            s += x;
        }
        #pragma unroll
        for (int o = 16; o > 0; o >>= 1) s += __shfl_xor_sync(0xffffffffu, s, o);
        float mean = s * (1.f/256.f);
        float q = 0.f;
        #pragma unroll
        for (int qq = 0; qq < 8; qq++){ float d = hv2[qq]-mean; q += d*d; }
        #pragma unroll
        for (int o = 16; o > 0; o >>= 1) q += __shfl_xor_sync(0xffffffffu, q, o);
        float rr = rsqrtf(q * (1.f/256.f) + 1e-5f);
        #pragma unroll
        for (int qq = 0; qq < 8; qq++){
            int d = qq*32 + lane;
            float lnv = (hv2[qq]-mean)*rr;
            float g = fmaf(iorow[d], lnv, iorow[256+d]);
            sm.p2.hsm[d][r] = fmaxf(g, 0.f);
        }
    }
    __syncthreads();

    // phase 3: y = tanh(h @ Wout + b); rows packed in f32x2 pairs via hsm
    const int n  = t & 255;
    const int g2 = t >> 8;                       // 0: rows 0-3, 1: rows 4-7
    unsigned long long yacc[2] = {0ull, 0ull};
    #pragma unroll 4
    for (int k = 0; k < 256; k++){
        unsigned long long w2 = pack2(Wout[k*256 + n]);
        ulonglong2 h2 = *(const ulonglong2*)&sm.p2.hsm[k][g2*4];
        ffma2(yacc[0], h2.x, w2);
        ffma2(yacc[1], h2.y, w2);
    }
    float bo = bout[n];
    bool masked = (iter > g_len[b]);
    float2 u0 = unpack2(yacc[0]);
    float2 u1 = unpack2(yacc[1]);
    float y0 = masked ? 0.f : tanhf(u0.x + bo);
    float y1 = masked ? 0.f : tanhf(u0.y + bo);
    float y2 = masked ? 0.f : tanhf(u1.x + bo);
    float y3 = masked ? 0.f : tanhf(u1.y + bo);
    g_h[(size_t)(row0 + 4*g2 + 0)*256 + n] = y0;
    g_h[(size_t)(row0 + 4*g2 + 1)*256 + n] = y1;
    g_h[(size_t)(row0 + 4*g2 + 2)*256 + n] = y2;
    g_h[(size_t)(row0 + 4*g2 + 3)*256 + n] = y3;
}

// ---------- epilogue ----------
__global__ void finalize_kernel(const float* __restrict__ root, float* __restrict__ out){
    int b = blockIdx.x, t = threadIdx.x;
    float s = 0.f;
    #pragma unroll 8
    for (int i = 0; i < 64; i++)
        s += g_h[(b*64 + i)*256 + t] * root[b*64 + i];
    out[b*256 + t] = s;
}

extern "C" void kernel_launch(void* const* d_in, const int* in_sizes, int n_in,
                              void* d_out, int out_size)
{
    const int*   tokens = (const int*)  d_in[0];
    const float* A      = (const float*)d_in[1];
    const float* root   = (const float*)d_in[2];
    const float* emb    = (const float*)d_in[3];
    const float* Wp     = (const float*)d_in[4];
    const float* bp     = (const float*)d_in[5];
    const float* Win    = (const float*)d_in[6];
    const float* bin    = (const float*)d_in[7];
    const float* Wout   = (const float*)d_in[8];
    const float* bout   = (const float*)d_in[9];
    float* out = (float*)d_out;

    float *px, *pio, *pp, *ph;
    cudaGetSymbolAddress((void**)&px,  g_x);
    cudaGetSymbolAddress((void**)&pio, g_io);
    cudaGetSymbolAddress((void**)&pp,  g_p);
    cudaGetSymbolAddress((void**)&ph,  g_h);

    gather_init_kernel<<<NBL, ND>>>(tokens, emb);
    length_kernel<<<1, NB>>>(tokens);
    gemm_kernel<false><<<dim3(16, 3), 256>>>(px, Win, bin, pio, 768);

    for (int it = 0; it < 64; it++){
        int i = 64 - it;
        gemm_kernel<true><<<dim3(16, 8), 256>>>(ph, Wp, bp, pp, 2048);
        step_kernel<<<128, 512>>>(A, Wout, bout, i);
    }

    finalize_kernel<<<16, 256>>>(root, out);
}

// round 5
// speedup vs baseline: 1.7003x; 1.1209x over previous
#include <cuda_runtime.h>

#define NBLOCKS 128
typedef unsigned long long ull;

__device__ __align__(16) float g_x [1024*256];
__device__ __align__(16) float g_io[1024*768];   // shift|scale|proj_x
__device__ __align__(16) float g_p [1024*2048];
__device__ __align__(16) float g_h [1024*256];
__device__ int g_len[16];
__device__ unsigned g_cnt = 0, g_gen = 0;

// ---------- packed fp32x2 helpers ----------
__device__ __forceinline__ ull pack2(float v){
    ull r; asm("mov.b64 %0, {%1, %1};" : "=l"(r) : "f"(v)); return r;
}
__device__ __forceinline__ ull packxy(float x, float y){
    ull r; asm("mov.b64 %0, {%1, %2};" : "=l"(r) : "f"(x), "f"(y)); return r;
}
__device__ __forceinline__ float2 unpack2(ull v){
    float2 r; asm("mov.b64 {%0, %1}, %2;" : "=f"(r.x), "=f"(r.y) : "l"(v)); return r;
}
__device__ __forceinline__ void ffma2(ull& d, ull a, ull b){
    asm("fma.rn.f32x2 %0, %1, %2, %0;" : "+l"(d) : "l"(a), "l"(b));
}
__device__ __forceinline__ void cpa16(void* s, const void* g){
    unsigned ss = (unsigned)__cvta_generic_to_shared(s);
    asm volatile("cp.async.cg.shared.global [%0], [%1], 16;\n" :: "r"(ss), "l"(g));
}
#define CPA_COMMIT() asm volatile("cp.async.commit_group;\n" ::: "memory")
#define CPA_WAIT0()  asm volatile("cp.async.wait_group 0;\n" ::: "memory")

// ---------- shared memory union ----------
struct GemmSm { float Hs[2][16*64]; float Ws[2][16*256]; float red[16][8][2]; }; // 41 KB
struct Step1Sm { ull As[256][8]; };                                              // 16 KB
struct Step2Sm { float ls[4][8][256]; float hsm[256][12]; };                     // 44 KB
union SmU { GemmSm g; Step1Sm a; Step2Sm p; };

// ---------- grid-wide barrier (all 128 blocks resident) ----------
__device__ __forceinline__ void grid_sync(){
    __threadfence();            // release: make this thread's writes GPU-visible
    __syncthreads();
    if (threadIdx.x == 0){
        unsigned my = *(volatile unsigned*)&g_gen;
        if (atomicAdd(&g_cnt, 1u) == NBLOCKS - 1u){
            g_cnt = 0;
            __threadfence();
            atomicAdd(&g_gen, 1u);
        } else {
            while (*(volatile unsigned*)&g_gen == my) __nanosleep(64);
        }
        __threadfence();        // acquire: CCTL.IVALL flushes this SM's L1D
    }
    __syncthreads();
}

// ---------- GEMM phase: M=1024,K=256; tile BM=64,BN=256,BK=16; 512 thr ----------
// warp tile: 8 rows x 128 cols; per thread 8x4 (f32x2 over col pairs)
__device__ void gemm_phase(const float* __restrict__ H, const float* __restrict__ W,
                           const float* __restrict__ bias, float* __restrict__ outp,
                           int N, int tiles_n, bool do_ln, SmU& sm)
{
    const int bid = blockIdx.x;
    if (bid >= 16*tiles_n) return;
    const int t = threadIdx.x;
    const int m0 = (bid / tiles_n) * 64;
    const int n0 = (bid % tiles_n) * 256;
    const int w = t >> 5, lane = t & 31;
    const int rg = (w & 7) * 8;                 // rows rg..rg+7
    const int cg = ((w >> 3) << 7) + lane*4;    // 4 cols

    const bool hload = t < 256;
    const int hr  = t & 63;
    const int hc4 = ((t >> 6) & 3) * 4;
    const int wk  = t >> 5;
    const int wn  = (t & 31) * 8;

    const float* Hg = H + (size_t)(m0 + hr)*256 + hc4;
    const float* Wg = W + (size_t)wk*N + n0 + wn;

    ull acc[8][2];
    #pragma unroll
    for (int i = 0; i < 8; i++){ acc[i][0] = 0ull; acc[i][1] = 0ull; }

    // stage 0
    float4 hv;
    if (hload) hv = *(const float4*)Hg;
    cpa16(&sm.g.Ws[0][wk*256 + wn], Wg);
    cpa16(&sm.g.Ws[0][wk*256 + wn + 4], Wg + 4);
    CPA_COMMIT();
    if (hload){
        const float* hp = (const float*)&hv;
        #pragma unroll
        for (int i = 0; i < 4; i++) sm.g.Hs[0][(hc4+i)*64 + hr] = hp[i];
        hv = *(const float4*)(Hg + 16);
    }
    CPA_WAIT0();
    __syncthreads();

    for (int s = 0; s < 16; s++){
        const int cur = s & 1;
        if (s + 1 < 16){
            const int nxt = cur ^ 1;
            const float* Wg2 = Wg + (size_t)(s+1)*16*N;
            cpa16(&sm.g.Ws[nxt][wk*256 + wn], Wg2);
            cpa16(&sm.g.Ws[nxt][wk*256 + wn + 4], Wg2 + 4);
            CPA_COMMIT();
            if (hload){
                const float* hp = (const float*)&hv;
                #pragma unroll
                for (int i = 0; i < 4; i++) sm.g.Hs[nxt][(hc4+i)*64 + hr] = hp[i];
                if (s + 2 < 16) hv = *(const float4*)(Hg + (s+2)*16);
            }
        }
        #pragma unroll
        for (int k = 0; k < 16; k++){
            float4 a0 = *(const float4*)&sm.g.Hs[cur][k*64 + rg];      // broadcast
            float4 a1 = *(const float4*)&sm.g.Hs[cur][k*64 + rg + 4];  // broadcast
            ulonglong2 bb = *(const ulonglong2*)&sm.g.Ws[cur][k*256 + cg];
            ull aa;
            aa = pack2(a0.x); ffma2(acc[0][0],aa,bb.x); ffma2(acc[0][1],aa,bb.y);
            aa = pack2(a0.y); ffma2(acc[1][0],aa,bb.x); ffma2(acc[1][1],aa,bb.y);
            aa = pack2(a0.z); ffma2(acc[2][0],aa,bb.x); ffma2(acc[2][1],aa,bb.y);
            aa = pack2(a0.w); ffma2(acc[3][0],aa,bb.x); ffma2(acc[3][1],aa,bb.y);
            aa = pack2(a1.x); ffma2(acc[4][0],aa,bb.x); ffma2(acc[4][1],aa,bb.y);
            aa = pack2(a1.y); ffma2(acc[5][0],aa,bb.x); ffma2(acc[5][1],aa,bb.y);
            aa = pack2(a1.z); ffma2(acc[6][0],aa,bb.x); ffma2(acc[6][1],aa,bb.y);
            aa = pack2(a1.w); ffma2(acc[7][0],aa,bb.x); ffma2(acc[7][1],aa,bb.y);
        }
        CPA_WAIT0();
        __syncthreads();
    }

    float bv[4];
    #pragma unroll
    for (int j = 0; j < 4; j++) bv[j] = bias[n0 + cg + j];

    float v[8][4];
    #pragma unroll
    for (int i = 0; i < 8; i++){
        float2 u0 = unpack2(acc[i][0]);
        float2 u1 = unpack2(acc[i][1]);
        v[i][0] = u0.x + bv[0]; v[i][1] = u0.y + bv[1];
        v[i][2] = u1.x + bv[2]; v[i][3] = u1.y + bv[3];
    }

    if (do_ln){
        // each row's 256 cols live in warps w and w^8 -> pairwise combine via smem
        float s1[8], s2[8];
        #pragma unroll
        for (int i = 0; i < 8; i++){
            float a = v[i][0]+v[i][1]+v[i][2]+v[i][3];
            float q = v[i][0]*v[i][0]+v[i][1]*v[i][1]+v[i][2]*v[i][2]+v[i][3]*v[i][3];
            #pragma unroll
            for (int o = 16; o > 0; o >>= 1){
                a += __shfl_xor_sync(0xffffffffu, a, o);
                q += __shfl_xor_sync(0xffffffffu, q, o);
            }
            s1[i] = a; s2[i] = q;
        }
        if (lane < 8){ sm.g.red[w][lane][0] = s1[lane]; sm.g.red[w][lane][1] = s2[lane]; }
        __syncthreads();
        const int pw = w ^ 8;
        #pragma unroll
        for (int i = 0; i < 8; i++){
            float tot1 = s1[i] + sm.g.red[pw][i][0];
            float tot2 = s2[i] + sm.g.red[pw][i][1];
            float mean = tot1 * (1.f/256.f);
            float var  = tot2 * (1.f/256.f) - mean*mean;
            float rstd = rsqrtf(var + 1e-5f);
            #pragma unroll
            for (int j = 0; j < 4; j++) v[i][j] = (v[i][j] - mean) * rstd;
        }
    }

    #pragma unroll
    for (int i = 0; i < 8; i++){
        float4 o4; o4.x=v[i][0]; o4.y=v[i][1]; o4.z=v[i][2]; o4.w=v[i][3];
        *(float4*)(outp + (size_t)(m0 + rg + i)*N + n0 + cg) = o4;
    }
}

// ---------- step phase: block=(b, 8 j), 512 threads ----------
__device__ void step_phase(const float* __restrict__ A, const float* __restrict__ Wout,
                           const float* __restrict__ bout, int iter, SmU& sm)
{
    const int t  = threadIdx.x;
    const int b  = blockIdx.x >> 3;
    const int j0 = (blockIdx.x & 7) * 8;
    const int row0 = b*64 + j0;

    // stage A packed over k-pairs
    const float* Ab = A + b*32768 + j0*8;
    #pragma unroll
    for (int idx = 0; idx < 4; idx++){
        int e = idx*512 + t;
        int kp = e >> 3, jj = e & 7;
        int k0 = kp*2;
        int base = (k0 >> 3)*512 + jj*8 + (k0 & 7);
        sm.a.As[kp][jj] = packxy(Ab[base], Ab[base + 1]);
    }
    __syncthreads();

    // phase 1: einsum, FFMA2 packed over k-pairs
    const int tx = t & 127;
    const int ty = t >> 7;
    ull acc[8][2];
    #pragma unroll
    for (int jj = 0; jj < 8; jj++){ acc[jj][0] = 0ull; acc[jj][1] = 0ull; }

    const float* pb = g_p + (size_t)(b*64 + ty*16)*2048 + tx;
    #pragma unroll 2
    for (int ii = 0; ii < 16; ii++){
        const float* pr = pb + ii*2048;
        #pragma unroll
        for (int hp = 0; hp < 4; hp++){
            ull p0 = packxy(pr[hp*512],       pr[hp*512 + 256]);
            ull p1 = packxy(pr[hp*512 + 128], pr[hp*512 + 384]);
            const int kp = (ty*16 + ii)*4 + hp;
            ulonglong2 A01 = *(const ulonglong2*)&sm.a.As[kp][0];
            ulonglong2 A23 = *(const ulonglong2*)&sm.a.As[kp][2];
            ulonglong2 A45 = *(const ulonglong2*)&sm.a.As[kp][4];
            ulonglong2 A67 = *(const ulonglong2*)&sm.a.As[kp][6];
            ffma2(acc[0][0], A01.x, p0); ffma2(acc[0][1], A01.x, p1);
            ffma2(acc[1][0], A01.y, p0); ffma2(acc[1][1], A01.y, p1);
            ffma2(acc[2][0], A23.x, p0); ffma2(acc[2][1], A23.x, p1);
            ffma2(acc[3][0], A23.y, p0); ffma2(acc[3][1], A23.y, p1);
            ffma2(acc[4][0], A45.x, p0); ffma2(acc[4][1], A45.x, p1);
            ffma2(acc[5][0], A45.y, p0); ffma2(acc[5][1], A45.y, p1);
            ffma2(acc[6][0], A67.x, p0); ffma2(acc[6][1], A67.x, p1);
            ffma2(acc[7][0], A67.y, p0); ffma2(acc[7][1], A67.y, p1);
        }
    }
    __syncthreads();
    #pragma unroll
    for (int jj = 0; jj < 8; jj++){
        float2 u0 = unpack2(acc[jj][0]);
        float2 u1 = unpack2(acc[jj][1]);
        sm.p.ls[ty][jj][tx]       = u0.x + u0.y;
        sm.p.ls[ty][jj][tx + 128] = u1.x + u1.y;
    }
    __syncthreads();

    // phase 2
    const int w = t >> 5, lane = t & 31;
    if (w < 8){
        const int r = w;
        const float* iorow = g_io + (size_t)(row0 + r)*768;
        float hv2[8];
        float s = 0.f;
        #pragma unroll
        for (int qq = 0; qq < 8; qq++){
            int d = qq*32 + lane;
            float x = sm.p.ls[0][r][d] + sm.p.ls[1][r][d]
                    + sm.p.ls[2][r][d] + sm.p.ls[3][r][d];
            x = x - tanhf(x);
            x += iorow[512 + d];
            hv2[qq] = x;
            s += x;
        }
        #pragma unroll
        for (int o = 16; o > 0; o >>= 1) s += __shfl_xor_sync(0xffffffffu, s, o);
        float mean = s * (1.f/256.f);
        float q = 0.f;
        #pragma unroll
        for (int qq = 0; qq < 8; qq++){ float d = hv2[qq]-mean; q += d*d; }
        #pragma unroll
        for (int o = 16; o > 0; o >>= 1) q += __shfl_xor_sync(0xffffffffu, q, o);
        float rr = rsqrtf(q * (1.f/256.f) + 1e-5f);
        #pragma unroll
        for (int qq = 0; qq < 8; qq++){
            int d = qq*32 + lane;
            float lnv = (hv2[qq]-mean)*rr;
            float g = fmaf(iorow[d], lnv, iorow[256+d]);
            sm.p.hsm[d][r] = fmaxf(g, 0.f);
        }
    }
    __syncthreads();

    // phase 3
    const int n  = t & 255;
    const int g2 = t >> 8;
    ull yacc[2] = {0ull, 0ull};
    #pragma unroll 4
    for (int k = 0; k < 256; k++){
        ull w2 = pack2(Wout[k*256 + n]);
        ulonglong2 h2 = *(const ulonglong2*)&sm.p.hsm[k][g2*4];
        ffma2(yacc[0], h2.x, w2);
        ffma2(yacc[1], h2.y, w2);
    }
    float bo = bout[n];
    bool masked = (iter > g_len[b]);
    float2 u0 = unpack2(yacc[0]);
    float2 u1 = unpack2(yacc[1]);
    g_h[(size_t)(row0 + 4*g2 + 0)*256 + n] = masked ? 0.f : tanhf(u0.x + bo);
    g_h[(size_t)(row0 + 4*g2 + 1)*256 + n] = masked ? 0.f : tanhf(u0.y + bo);
    g_h[(size_t)(row0 + 4*g2 + 2)*256 + n] = masked ? 0.f : tanhf(u1.x + bo);
    g_h[(size_t)(row0 + 4*g2 + 3)*256 + n] = masked ? 0.f : tanhf(u1.y + bo);
}

// ---------- single persistent kernel ----------
__global__ void __launch_bounds__(512) fused_kernel(
    const int* __restrict__ tokens, const float* __restrict__ A,
    const float* __restrict__ root, const float* __restrict__ emb,
    const float* __restrict__ Wp,   const float* __restrict__ bp,
    const float* __restrict__ Win,  const float* __restrict__ bin,
    const float* __restrict__ Wout, const float* __restrict__ bout,
    float* __restrict__ out)
{
    __shared__ __align__(16) SmU sm;
    const int bid = blockIdx.x;
    const int t = threadIdx.x;

    // prologue: gather embeddings, zero h, lengths
    {
        int idx = bid*512 + t;              // one float4 per thread (1024*256/4 = 65536)
        int row = idx >> 6;
        int c4  = (idx & 63) * 4;
        int b = row >> 6, l = row & 63;
        int tok = tokens[l*16 + b];
        *(float4*)&g_x[row*256 + c4] = *(const float4*)&emb[(size_t)tok*256 + c4];
        float4 z; z.x=z.y=z.z=z.w=0.f;
        *(float4*)&g_h[row*256 + c4] = z;
        if (bid == 0 && t < 16){
            int c = 0;
            for (int l2 = 0; l2 < 64; l2++) c += (tokens[l2*16 + t] != 0);
            g_len[t] = c;
        }
    }
    grid_sync();

    // hoisted in_proj: g_io = g_x @ Win + bin  (blocks 0..47)
    gemm_phase(g_x, Win, bin, g_io, 768, 3, false, sm);
    grid_sync();

    // 64-step recurrence
    for (int it = 0; it < 64; it++){
        gemm_phase(g_h, Wp, bp, g_p, 2048, 8, true, sm);   // p = LN(h @ Wp + bp)
        grid_sync();
        step_phase(A, Wout, bout, 64 - it, sm);            // einsum..mask -> h
        grid_sync();
    }

    // epilogue: out[b][d] = sum_i h[b,i,d] * root[b,i]
    if (bid < 16 && t < 256){
        float s = 0.f;
        #pragma unroll 8
        for (int i = 0; i < 64; i++)
            s += g_h[(size_t)(bid*64 + i)*256 + t] * root[bid*64 + i];
        out[bid*256 + t] = s;
    }
}

extern "C" void kernel_launch(void* const* d_in, const int* in_sizes, int n_in,
                              void* d_out, int out_size)
{
    const int*   tokens = (const int*)  d_in[0];
    const float* A      = (const float*)d_in[1];
    const float* root   = (const float*)d_in[2];
    const float* emb    = (const float*)d_in[3];
    const float* Wp     = (const float*)d_in[4];
    const float* bp     = (const float*)d_in[5];
    const float* Win    = (const float*)d_in[6];
    const float* bin    = (const float*)d_in[7];
    const float* Wout   = (const float*)d_in[8];
    const float* bout   = (const float*)d_in[9];

    fused_kernel<<<NBLOCKS, 512>>>(tokens, A, root, emb, Wp, bp, Win, bin,
                                   Wout, bout, (float*)d_out);
}

// round 7
// speedup vs baseline: 2.0714x; 1.2182x over previous
#include <cuda_runtime.h>

#define NBLOCKS 128
typedef unsigned long long ull;

__device__ __align__(16) float g_x  [1024*256];
__device__ __align__(16) float g_io [1024*768];    // shift|scale|proj_x
__device__ __align__(16) float g_p  [1024*2048];
__device__ __align__(16) float g_h  [1024*256];
__device__ __align__(16) float g_wpR [256*2048];   // Wp, tf32-rounded, [k][n]
__device__ __align__(16) float g_winR[256*768];    // Win, tf32-rounded, [k][n]
__device__ int g_len[16];
__device__ unsigned g_cnt = 0, g_gen = 0;

// ---------- helpers ----------
__device__ __forceinline__ ull pack2(float v){
    ull r; asm("mov.b64 %0, {%1, %1};" : "=l"(r) : "f"(v)); return r;
}
__device__ __forceinline__ ull packxy(float x, float y){
    ull r; asm("mov.b64 %0, {%1, %2};" : "=l"(r) : "f"(x), "f"(y)); return r;
}
__device__ __forceinline__ float2 unpack2(ull v){
    float2 r; asm("mov.b64 {%0, %1}, %2;" : "=f"(r.x), "=f"(r.y) : "l"(v)); return r;
}
__device__ __forceinline__ void ffma2(ull& d, ull a, ull b){
    asm("fma.rn.f32x2 %0, %1, %2, %0;" : "+l"(d) : "l"(a), "l"(b));
}
__device__ __forceinline__ void cpa16(void* s, const void* g){
    unsigned ss = (unsigned)__cvta_generic_to_shared(s);
    asm volatile("cp.async.cg.shared.global [%0], [%1], 16;\n" :: "r"(ss), "l"(g));
}
#define CPA_COMMIT() asm volatile("cp.async.commit_group;\n" ::: "memory")
#define CPA_WAIT0()  asm volatile("cp.async.wait_group 0;\n" ::: "memory")

__device__ __forceinline__ float to_tf32(float x){
    float r; asm("cvt.rna.tf32.f32 %0, %1;" : "=f"(r) : "f"(x)); return r;
}

// legacy HMMA: m16n8k8 tf32 (sm_80+, valid on base sm_103 target)
__device__ __forceinline__ void mma_tf32(float* d, const unsigned* a, const unsigned* b){
    asm volatile(
        "mma.sync.aligned.m16n8k8.row.col.f32.tf32.tf32.f32 "
        "{%0,%1,%2,%3}, {%4,%5,%6,%7}, {%8,%9}, {%0,%1,%2,%3};"
        : "+f"(d[0]), "+f"(d[1]), "+f"(d[2]), "+f"(d[3])
        : "r"(a[0]), "r"(a[1]), "r"(a[2]), "r"(a[3]), "r"(b[0]), "r"(b[1]));
}

// ---------- dynamic smem ----------
// gemm: Asm [2][64*36]f at 0 (18432B); Bsm [2][32*264]f at 18432 (67584B) = 86016B
// step: As[256][8] ull (16KB) | Step2Sm (44KB)
#define SMEM_DYN 87040
struct Step2Sm { float ls[4][8][256]; float hsm[256][12]; };

// ---------- grid-wide barrier (128 blocks co-resident) ----------
__device__ __forceinline__ void grid_sync(){
    __threadfence();
    __syncthreads();
    if (threadIdx.x == 0){
        unsigned my = *(volatile unsigned*)&g_gen;
        if (atomicAdd(&g_cnt, 1u) == NBLOCKS - 1u){
            g_cnt = 0;
            __threadfence();
            atomicAdd(&g_gen, 1u);
        } else {
            while (*(volatile unsigned*)&g_gen == my) __nanosleep(64);
        }
        __threadfence();
    }
    __syncthreads();
}

// ---------- HMMA GEMM: D = A[1024x256] @ B[256xN] (+bias, +optional 256-col LN) ----------
// block tile 64x256; 16 warps as 2m x 8n; warp tile 32x32 (2 m16-groups x 4 n8-frags)
__device__ void gemm_mma(const float* __restrict__ Asrc, const float* __restrict__ Bsrc,
                         const float* __restrict__ bias, float* __restrict__ outp,
                         int N, int bn_cnt, bool do_ln, char* dyn,
                         float (*s_red)[8][2])
{
    const int bid = blockIdx.x;
    if (bid >= 16*bn_cnt) return;
    const int t = threadIdx.x, w = t >> 5, lane = t & 31;
    const int m0 = (bid / bn_cnt) * 64;
    const int n0 = (bid % bn_cnt) * 256;
    const int wm = w & 1, wn = w >> 1;
    const int r4 = lane >> 2, q = lane & 3;

    float* Asm = (float*)dyn;              // [2][64*36], row stride 36 (bank-safe)
    float* Bsm = (float*)(dyn + 18432);    // [2][32*264], row stride 264 (bank-safe)

    float acc[2][4][4];
    #pragma unroll
    for (int g = 0; g < 2; g++)
        #pragma unroll
        for (int f = 0; f < 4; f++)
            #pragma unroll
            for (int rr = 0; rr < 4; rr++) acc[g][f][rr] = 0.f;

    const int am  = t >> 3,  ak4 = (t & 7) * 4;   // A loader: row, 4k
    // B loader: 4x per thread

    // ---- chunk 0 ----
    cpa16(Asm + am*36 + ak4, Asrc + (size_t)(m0 + am)*256 + ak4);
    #pragma unroll
    for (int i = 0; i < 4; i++){
        int e = t + i*512, k = e >> 6, n4 = (e & 63) * 4;
        cpa16(Bsm + k*264 + n4, Bsrc + (size_t)k*N + n0 + n4);
    }
    CPA_COMMIT(); CPA_WAIT0();
    __syncthreads();

    for (int c = 0; c < 8; c++){
        const int buf = c & 1;
        if (c < 7){
            const int nb = buf ^ 1;
            cpa16(Asm + nb*2304 + am*36 + ak4,
                  Asrc + (size_t)(m0 + am)*256 + (c+1)*32 + ak4);
            #pragma unroll
            for (int i = 0; i < 4; i++){
                int e = t + i*512, k = e >> 6, n4 = (e & 63) * 4;
                cpa16(Bsm + nb*8448 + k*264 + n4,
                      Bsrc + (size_t)((c+1)*32 + k)*N + n0 + n4);
            }
            CPA_COMMIT();
        }
        const float* Ab = Asm + buf*2304 + (wm*32 + r4)*36 + q;
        const float* Bb = Bsm + buf*8448 + q*264 + wn*32 + r4;
        #pragma unroll
        for (int ks = 0; ks < 4; ks++){
            unsigned a[2][4], b[4][2];
            const float* Ak = Ab + ks*8;
            #pragma unroll
            for (int g = 0; g < 2; g++){
                const float* Ag = Ak + g*16*36;
                a[g][0] = __float_as_uint(Ag[0]);
                a[g][1] = __float_as_uint(Ag[8*36]);
                a[g][2] = __float_as_uint(Ag[4]);
                a[g][3] = __float_as_uint(Ag[8*36 + 4]);
            }
            const float* Bk = Bb + ks*8*264;
            #pragma unroll
            for (int f = 0; f < 4; f++){
                b[f][0] = __float_as_uint(Bk[f*8]);
                b[f][1] = __float_as_uint(Bk[4*264 + f*8]);
            }
            #pragma unroll
            for (int g = 0; g < 2; g++)
                #pragma unroll
                for (int f = 0; f < 4; f++)
                    mma_tf32(acc[g][f], a[g], b[f]);
        }
        if (c < 7) CPA_WAIT0();
        __syncthreads();
    }

    // ---- epilogue: bias, LN, store ----
    #pragma unroll
    for (int f = 0; f < 4; f++){
        float b0 = bias[n0 + wn*32 + f*8 + 2*q];
        float b1 = bias[n0 + wn*32 + f*8 + 2*q + 1];
        #pragma unroll
        for (int g = 0; g < 2; g++){
            acc[g][f][0] += b0; acc[g][f][1] += b1;
            acc[g][f][2] += b0; acc[g][f][3] += b1;
        }
    }

    if (do_ln){
        #pragma unroll
        for (int g = 0; g < 2; g++)
            #pragma unroll
            for (int h = 0; h < 2; h++){
                float s1 = 0.f, s2 = 0.f;
                #pragma unroll
                for (int f = 0; f < 4; f++){
                    float v0 = acc[g][f][2*h], v1 = acc[g][f][2*h + 1];
                    s1 += v0 + v1; s2 += v0*v0 + v1*v1;
                }
                s1 += __shfl_xor_sync(0xffffffffu, s1, 1);
                s2 += __shfl_xor_sync(0xffffffffu, s2, 1);
                s1 += __shfl_xor_sync(0xffffffffu, s1, 2);
                s2 += __shfl_xor_sync(0xffffffffu, s2, 2);
                if (q == 0){
                    int rl = wm*32 + g*16 + h*8 + r4;
                    s_red[rl][wn][0] = s1; s_red[rl][wn][1] = s2;
                }
            }
        __syncthreads();
        #pragma unroll
        for (int g = 0; g < 2; g++)
            #pragma unroll
            for (int h = 0; h < 2; h++){
                int rl = wm*32 + g*16 + h*8 + r4;
                float t1 = 0.f, t2 = 0.f;
                #pragma unroll
                for (int j = 0; j < 8; j++){ t1 += s_red[rl][j][0]; t2 += s_red[rl][j][1]; }
                float mean = t1 * (1.f/256.f);
                float var  = t2 * (1.f/256.f) - mean*mean;
                float rstd = rsqrtf(var + 1e-5f);
                #pragma unroll
                for (int f = 0; f < 4; f++){
                    acc[g][f][2*h]   = (acc[g][f][2*h]   - mean) * rstd;
                    acc[g][f][2*h+1] = (acc[g][f][2*h+1] - mean) * rstd;
                }
            }
    }

    #pragma unroll
    for (int g = 0; g < 2; g++)
        #pragma unroll
        for (int h = 0; h < 2; h++){
            int row = m0 + wm*32 + g*16 + h*8 + r4;
            float* op = outp + (size_t)row*N + n0 + wn*32 + 2*q;
            #pragma unroll
            for (int f = 0; f < 4; f++){
                float2 o2; o2.x = acc[g][f][2*h]; o2.y = acc[g][f][2*h+1];
                *(float2*)(op + f*8) = o2;
            }
        }
    __syncthreads();
}

// ---------- step phase (FFMA2): block=(b, 8 j), 512 threads ----------
__device__ void step_phase(const float* __restrict__ A, const float* __restrict__ Wout,
                           const float* __restrict__ bout, int iter, char* dyn)
{
    ull (*As)[8] = (ull(*)[8])dyn;
    Step2Sm* p2  = (Step2Sm*)dyn;

    const int t  = threadIdx.x;
    const int b  = blockIdx.x >> 3;
    const int j0 = (blockIdx.x & 7) * 8;
    const int row0 = b*64 + j0;

    const float* Ab = A + b*32768 + j0*8;
    #pragma unroll
    for (int idx = 0; idx < 4; idx++){
        int e = idx*512 + t;
        int kp = e >> 3, jj = e & 7;
        int k0 = kp*2;
        int base = (k0 >> 3)*512 + jj*8 + (k0 & 7);
        As[kp][jj] = packxy(Ab[base], Ab[base + 1]);
    }
    __syncthreads();

    const int tx = t & 127;
    const int ty = t >> 7;
    ull acc[8][2];
    #pragma unroll
    for (int jj = 0; jj < 8; jj++){ acc[jj][0] = 0ull; acc[jj][1] = 0ull; }

    const float* pb = g_p + (size_t)(b*64 + ty*16)*2048 + tx;
    #pragma unroll 2
    for (int ii = 0; ii < 16; ii++){
        const float* pr = pb + ii*2048;
        #pragma unroll
        for (int hp = 0; hp < 4; hp++){
            ull p0 = packxy(pr[hp*512],       pr[hp*512 + 256]);
            ull p1 = packxy(pr[hp*512 + 128], pr[hp*512 + 384]);
            const int kp = (ty*16 + ii)*4 + hp;
            ulonglong2 A01 = *(const ulonglong2*)&As[kp][0];
            ulonglong2 A23 = *(const ulonglong2*)&As[kp][2];
            ulonglong2 A45 = *(const ulonglong2*)&As[kp][4];
            ulonglong2 A67 = *(const ulonglong2*)&As[kp][6];
            ffma2(acc[0][0], A01.x, p0); ffma2(acc[0][1], A01.x, p1);
            ffma2(acc[1][0], A01.y, p0); ffma2(acc[1][1], A01.y, p1);
            ffma2(acc[2][0], A23.x, p0); ffma2(acc[2][1], A23.x, p1);
            ffma2(acc[3][0], A23.y, p0); ffma2(acc[3][1], A23.y, p1);
            ffma2(acc[4][0], A45.x, p0); ffma2(acc[4][1], A45.x, p1);
            ffma2(acc[5][0], A45.y, p0); ffma2(acc[5][1], A45.y, p1);
            ffma2(acc[6][0], A67.x, p0); ffma2(acc[6][1], A67.x, p1);
            ffma2(acc[7][0], A67.y, p0); ffma2(acc[7][1], A67.y, p1);
        }
    }
    __syncthreads();
    #pragma unroll
    for (int jj = 0; jj < 8; jj++){
        float2 u0 = unpack2(acc[jj][0]);
        float2 u1 = unpack2(acc[jj][1]);
        p2->ls[ty][jj][tx]       = u0.x + u0.y;
        p2->ls[ty][jj][tx + 128] = u1.x + u1.y;
    }
    __syncthreads();

    const int w = t >> 5, lane = t & 31;
    if (w < 8){
        const int r = w;
        const float* iorow = g_io + (size_t)(row0 + r)*768;
        float hv2[8];
        float s = 0.f;
        #pragma unroll
        for (int qq = 0; qq < 8; qq++){
            int d = qq*32 + lane;
            float x = p2->ls[0][r][d] + p2->ls[1][r][d]
                    + p2->ls[2][r][d] + p2->ls[3][r][d];
            x = x - tanhf(x);
            x += iorow[512 + d];
            hv2[qq] = x;
            s += x;
        }
        #pragma unroll
        for (int o = 16; o > 0; o >>= 1) s += __shfl_xor_sync(0xffffffffu, s, o);
        float mean = s * (1.f/256.f);
        float qv = 0.f;
        #pragma unroll
        for (int qq = 0; qq < 8; qq++){ float d = hv2[qq]-mean; qv += d*d; }
        #pragma unroll
        for (int o = 16; o > 0; o >>= 1) qv += __shfl_xor_sync(0xffffffffu, qv, o);
        float rr = rsqrtf(qv * (1.f/256.f) + 1e-5f);
        #pragma unroll
        for (int qq = 0; qq < 8; qq++){
            int d = qq*32 + lane;
            float lnv = (hv2[qq]-mean)*rr;
            float g = fmaf(iorow[d], lnv, iorow[256+d]);
            p2->hsm[d][r] = fmaxf(g, 0.f);
        }
    }
    __syncthreads();

    const int n  = t & 255;
    const int g2 = t >> 8;
    ull yacc[2] = {0ull, 0ull};
    #pragma unroll 4
    for (int k = 0; k < 256; k++){
        ull w2 = pack2(Wout[k*256 + n]);
        ulonglong2 h2 = *(const ulonglong2*)&p2->hsm[k][g2*4];
        ffma2(yacc[0], h2.x, w2);
        ffma2(yacc[1], h2.y, w2);
    }
    float bo = bout[n];
    bool masked = (iter > g_len[b]);
    float2 u0 = unpack2(yacc[0]);
    float2 u1 = unpack2(yacc[1]);
    // tf32-round h so the next HMMA gemm sees exactly-representable A
    g_h[(size_t)(row0 + 4*g2 + 0)*256 + n] = masked ? 0.f : to_tf32(tanhf(u0.x + bo));
    g_h[(size_t)(row0 + 4*g2 + 1)*256 + n] = masked ? 0.f : to_tf32(tanhf(u0.y + bo));
    g_h[(size_t)(row0 + 4*g2 + 2)*256 + n] = masked ? 0.f : to_tf32(tanhf(u1.x + bo));
    g_h[(size_t)(row0 + 4*g2 + 3)*256 + n] = masked ? 0.f : to_tf32(tanhf(u1.y + bo));
}

// ---------- single persistent kernel ----------
__global__ void __launch_bounds__(512) fused_kernel(
    const int* __restrict__ tokens, const float* __restrict__ A,
    const float* __restrict__ root, const float* __restrict__ emb,
    const float* __restrict__ Wp,   const float* __restrict__ bp,
    const float* __restrict__ Win,  const float* __restrict__ bin,
    const float* __restrict__ Wout, const float* __restrict__ bout,
    float* __restrict__ out)
{
    extern __shared__ char smraw[];
    char* dyn = (char*)((((size_t)smraw) + 1023) & ~(size_t)1023);
    __shared__ float s_red[64][8][2];

    const int bid = blockIdx.x;
    const int t = threadIdx.x;

    // prologue: gather (tf32-rounded), zero h, lengths, tf32-rounded weight copies
    {
        int idx = bid*512 + t;                   // 65536 threads, 1 float4 each
        int row = idx >> 6;
        int c4  = (idx & 63) * 4;
        int b = row >> 6, l = row & 63;
        int tok = tokens[l*16 + b];
        float4 e4 = *(const float4*)&emb[(size_t)tok*256 + c4];
        e4.x = to_tf32(e4.x); e4.y = to_tf32(e4.y); e4.z = to_tf32(e4.z); e4.w = to_tf32(e4.w);
        *(float4*)&g_x[row*256 + c4] = e4;
        float4 z; z.x=z.y=z.z=z.w=0.f;
        *(float4*)&g_h[row*256 + c4] = z;
        if (bid == 0 && t < 16){
            int c = 0;
            for (int l2 = 0; l2 < 64; l2++) c += (tokens[l2*16 + t] != 0);
            g_len[t] = c;
        }
        #pragma unroll
        for (int i = 0; i < 2; i++){             // WpR: 131072 float4
            int e = idx + i*65536;
            float4 v = *(const float4*)&Wp[(size_t)e*4];
            v.x = to_tf32(v.x); v.y = to_tf32(v.y); v.z = to_tf32(v.z); v.w = to_tf32(v.w);
            *(float4*)&g_wpR[(size_t)e*4] = v;
        }
        if (idx < 49152){                        // WinR: 49152 float4
            float4 v = *(const float4*)&Win[(size_t)idx*4];
            v.x = to_tf32(v.x); v.y = to_tf32(v.y); v.z = to_tf32(v.z); v.w = to_tf32(v.w);
            *(float4*)&g_winR[(size_t)idx*4] = v;
        }
    }
    grid_sync();

    // hoisted in_proj: g_io = g_x @ Win + bin (48 blocks active)
    gemm_mma(g_x, g_winR, bin, g_io, 768, 3, false, dyn, s_red);
    grid_sync();

    // 64-step recurrence
    for (int it = 0; it < 64; it++){
        gemm_mma(g_h, g_wpR, bp, g_p, 2048, 8, true, dyn, s_red);
        grid_sync();
        step_phase(A, Wout, bout, 64 - it, dyn);
        grid_sync();
    }

    // epilogue: out[b][d] = sum_i h[b,i,d] * root[b,i]
    if (bid < 16 && t < 256){
        float s = 0.f;
        #pragma unroll 8
        for (int i = 0; i < 64; i++)
            s += g_h[(size_t)(bid*64 + i)*256 + t] * root[bid*64 + i];
        out[bid*256 + t] = s;
    }
}

extern "C" void kernel_launch(void* const* d_in, const int* in_sizes, int n_in,
                              void* d_out, int out_size)
{
    const int*   tokens = (const int*)  d_in[0];
    const float* A      = (const float*)d_in[1];
    const float* root   = (const float*)d_in[2];
    const float* emb    = (const float*)d_in[3];
    const float* Wp     = (const float*)d_in[4];
    const float* bp     = (const float*)d_in[5];
    const float* Win    = (const float*)d_in[6];
    const float* bin    = (const float*)d_in[7];
    const float* Wout   = (const float*)d_in[8];
    const float* bout   = (const float*)d_in[9];

    cudaFuncSetAttribute(fused_kernel, cudaFuncAttributeMaxDynamicSharedMemorySize, SMEM_DYN);
    fused_kernel<<<NBLOCKS, 512, SMEM_DYN>>>(tokens, A, root, emb, Wp, bp, Win, bin,
                                             Wout, bout, (float*)d_out);
}